// round 1
// baseline (speedup 1.0000x reference)
#include <cuda_runtime.h>
#include <math.h>
#include <stdint.h>

typedef unsigned long long ull;

// ---------- f32x2 packed-FMA helpers (Blackwell, PTX-only path) ----------
__device__ __forceinline__ ull dup2(float v) {
    ull r;
    asm("mov.b64 %0, {%1, %1};" : "=l"(r) : "f"(v));
    return r;
}
__device__ __forceinline__ void fma2(ull& d, ull a, ull b) {
    asm("fma.rn.f32x2 %0, %1, %2, %0;" : "+l"(d) : "l"(a), "l"(b));
}
__device__ __forceinline__ void unpack2(ull v, float& lo, float& hi) {
    asm("mov.b64 {%0, %1}, %2;" : "=f"(lo), "=f"(hi) : "l"(v));
}

// ---------- problem constants ----------
#define HDIM 1024      // H
#define NDIM 2048      // 2H
#define NEXP 8
#define BM 64
#define BN 64
#define BK 16
#define NSPLIT 4
#define CHUNKS_PER (NDIM / BN / NSPLIT)   // 8

// scratch for cross-block reductions (no cudaMalloc allowed)
__device__ float g_usage[NEXP];
__device__ int   g_count;

// ---------- kernel 0: init ew = b2 (broadcast), zero scratch ----------
__global__ void init_kernel(float* __restrict__ ew, const float* __restrict__ b2, int n) {
    int i = blockIdx.x * blockDim.x + threadIdx.x;
    if (i < n) ew[i] = b2[i & 7];
    if (blockIdx.x == 0) {
        if (threadIdx.x < NEXP) g_usage[threadIdx.x] = 0.f;
        if (threadIdx.x == 0)   g_count = 0;
    }
}

// ---------- kernel 1: fused  ew += gelu(x@w1 + b1) @ w2  ----------
// block: 256 threads, tx = t&15 (N cols, TN=4), ty = t>>4 (M rows, TM=4)
// grid: (M/BM, NSPLIT); each block handles CHUNKS_PER chunks of 64 N-cols.
__global__ __launch_bounds__(256, 2)
void gemm_kernel(const float* __restrict__ x, const float* __restrict__ w1,
                 const float* __restrict__ b1, const float* __restrict__ w2,
                 float* __restrict__ ew)
{
    __shared__ float xs[BK][BM + 4];     // transposed x tile, pad 4 for store banks
    __shared__ float w1s[BK][BN];
    __shared__ float w2s[BN][9];         // pad to 9 to avoid read conflicts

    const int t  = threadIdx.x;
    const int tx = t & 15;
    const int ty = t >> 4;
    const int mBase = blockIdx.x * BM;

    // x-tile load mapping: one float4 per thread
    const int xr = t >> 2;               // row in tile 0..63
    const int xq = (t & 3) * 4;          // k-offset within BK
    // w1-tile load mapping: one float4 per thread
    const int wk = t >> 4;               // k row 0..15
    const int wn = (t & 15) * 4;         // n col 0..60

    const float* xg = x + (size_t)(mBase + xr) * HDIM + xq;

    float ew_part[4][NEXP];
#pragma unroll
    for (int i = 0; i < 4; ++i)
#pragma unroll
        for (int e = 0; e < NEXP; ++e) ew_part[i][e] = 0.f;

    for (int c = 0; c < CHUNKS_PER; ++c) {
        const int n0 = (blockIdx.y * CHUNKS_PER + c) * BN;

        // load w2 chunk [64 x 8] into padded smem
#pragma unroll
        for (int i = t; i < BN * NEXP; i += 256)
            w2s[i >> 3][i & 7] = w2[(size_t)n0 * NEXP + i];

        // accumulators: rows packed in pairs (f32x2), acc[i2][j]: rows 2*i2, 2*i2+1
        ull acc[2][4];
#pragma unroll
        for (int i2 = 0; i2 < 2; ++i2)
#pragma unroll
            for (int j = 0; j < 4; ++j) acc[i2][j] = 0ULL;

        const float* w1g = w1 + (size_t)wk * NDIM + n0 + wn;

        for (int kt = 0; kt < HDIM / BK; ++kt) {
            // issue global loads early
            float4 xv = *(const float4*)(xg + kt * BK);
            float4 wv = *(const float4*)(w1g + (size_t)kt * BK * NDIM);

            __syncthreads();             // previous tile fully consumed (also covers w2s)
            xs[xq + 0][xr] = xv.x;
            xs[xq + 1][xr] = xv.y;
            xs[xq + 2][xr] = xv.z;
            xs[xq + 3][xr] = xv.w;
            *(float4*)&w1s[wk][wn] = wv;
            __syncthreads();

#pragma unroll
            for (int k = 0; k < BK; ++k) {
                ull a01 = *(const ull*)&xs[k][ty * 4];
                ull a23 = *(const ull*)&xs[k][ty * 4 + 2];
                float4 bv = *(const float4*)&w1s[k][tx * 4];
                ull b0 = dup2(bv.x), b1d = dup2(bv.y), b2d = dup2(bv.z), b3d = dup2(bv.w);
                fma2(acc[0][0], a01, b0);  fma2(acc[1][0], a23, b0);
                fma2(acc[0][1], a01, b1d); fma2(acc[1][1], a23, b1d);
                fma2(acc[0][2], a01, b2d); fma2(acc[1][2], a23, b2d);
                fma2(acc[0][3], a01, b3d); fma2(acc[1][3], a23, b3d);
            }
        }

        // epilogue: +b1, exact GELU, contract with w2 chunk
#pragma unroll
        for (int j = 0; j < 4; ++j) {
            const float bb = __ldg(&b1[n0 + tx * 4 + j]);
            const float* w2row = &w2s[tx * 4 + j][0];
#pragma unroll
            for (int i2 = 0; i2 < 2; ++i2) {
                float vlo, vhi;
                unpack2(acc[i2][j], vlo, vhi);
                float v0 = vlo + bb, v1 = vhi + bb;
                float h0 = 0.5f * v0 * (1.0f + erff(v0 * 0.7071067811865475f));
                float h1 = 0.5f * v1 * (1.0f + erff(v1 * 0.7071067811865475f));
#pragma unroll
                for (int e = 0; e < NEXP; ++e) {
                    float w = w2row[e];
                    ew_part[2 * i2 + 0][e] = fmaf(h0, w, ew_part[2 * i2 + 0][e]);
                    ew_part[2 * i2 + 1][e] = fmaf(h1, w, ew_part[2 * i2 + 1][e]);
                }
            }
        }
        __syncthreads();                 // epilogue done before next w2s overwrite
    }

    // reduce over the 16 tx lanes (xor bits 0..3 stay inside each 16-lane half)
#pragma unroll
    for (int i = 0; i < 4; ++i) {
#pragma unroll
        for (int e = 0; e < NEXP; ++e) {
            float v = ew_part[i][e];
            v += __shfl_xor_sync(0xffffffffu, v, 8);
            v += __shfl_xor_sync(0xffffffffu, v, 4);
            v += __shfl_xor_sync(0xffffffffu, v, 2);
            v += __shfl_xor_sync(0xffffffffu, v, 1);
            if (tx == 0)
                atomicAdd(&ew[(size_t)(mBase + ty * 4 + i) * NEXP + e], v);
        }
    }
}

// ---------- kernel 2: top-2 + softmax + masks + usage reduction ----------
__global__ void topk_kernel(const float* __restrict__ ew, float* __restrict__ masks, int M) {
    __shared__ float susage[NEXP];
    __shared__ int   scount;
    const int t = threadIdx.x;
    if (t < NEXP) susage[t] = 0.f;
    if (t == 0)   scount = 0;
    __syncthreads();

    const int tok = blockIdx.x * blockDim.x + t;
    if (tok < M) {
        float v[NEXP];
        float4 a = *(const float4*)(ew + (size_t)tok * NEXP);
        float4 b = *(const float4*)(ew + (size_t)tok * NEXP + 4);
        v[0] = a.x; v[1] = a.y; v[2] = a.z; v[3] = a.w;
        v[4] = b.x; v[5] = b.y; v[6] = b.z; v[7] = b.w;

        int i1 = 0; float m1 = v[0];
#pragma unroll
        for (int e = 1; e < NEXP; ++e)
            if (v[e] > m1) { m1 = v[e]; i1 = e; }    // strict > : earliest idx on ties (lax.top_k)
        int i2 = -1; float m2 = -3.402823466e38f;
#pragma unroll
        for (int e = 0; e < NEXP; ++e)
            if (e != i1 && v[e] > m2) { m2 = v[e]; i2 = e; }

        float ex = expf(m2 - m1);
        float p1 = 1.f / (1.f + ex);
        float p2 = ex / (1.f + ex);

        float o[NEXP];
#pragma unroll
        for (int e = 0; e < NEXP; ++e)
            o[e] = (e == i1) ? p1 : ((e == i2) ? p2 : 0.f);
        float4 o0 = make_float4(o[0], o[1], o[2], o[3]);
        float4 o1 = make_float4(o[4], o[5], o[6], o[7]);
        *(float4*)(masks + (size_t)tok * NEXP)     = o0;
        *(float4*)(masks + (size_t)tok * NEXP + 4) = o1;

        atomicAdd(&susage[i1], p1);
        atomicAdd(&susage[i2], p2);
        int cnt = (p1 > 0.f) + (p2 > 0.f);
        atomicAdd(&scount, cnt);
    }
    __syncthreads();
    if (t < NEXP) atomicAdd(&g_usage[t], susage[t]);
    if (t == 0)   atomicAdd(&g_count, scount);
}

// ---------- kernel 3: losses + normalized usage ----------
__global__ void finish_kernel(float* __restrict__ tail, int M) {
    float u[NEXP];
    float s = 0.f;
#pragma unroll
    for (int e = 0; e < NEXP; ++e) { u[e] = g_usage[e]; s += u[e]; }
    float lb = 0.f;
#pragma unroll
    for (int e = 0; e < NEXP; ++e) {
        float un = u[e] / s;
        tail[1 + e] = un;                       // expert_usage (normalized)
        float d = un - 0.125f;
        lb += d * d;
    }
    lb *= (1.f / 8.f);                           // mean over E
    float sparsity = ((float)g_count / (float)M) * 0.5f;  // mean(count)/TOP_K
    tail[0] = lb + 0.1f * sparsity;              // total_loss
}

// ---------- launch ----------
extern "C" void kernel_launch(void* const* d_in, const int* in_sizes, int n_in,
                              void* d_out, int out_size) {
    const float* x  = (const float*)d_in[0];
    const float* w1 = (const float*)d_in[1];
    const float* b1 = (const float*)d_in[2];
    const float* w2 = (const float*)d_in[3];
    const float* b2 = (const float*)d_in[4];

    float* out = (float*)d_out;
    const int M = in_sizes[0] / HDIM;            // 16384 tokens

    float* ew    = out;                          // [M, 8]
    float* masks = out + (size_t)M * NEXP;       // [M, 8]
    float* tail  = out + (size_t)2 * M * NEXP;   // [loss, usage x 8]

    init_kernel<<<(M * NEXP + 255) / 256, 256>>>(ew, b2, M * NEXP);

    dim3 grid(M / BM, NSPLIT);
    gemm_kernel<<<grid, 256>>>(x, w1, b1, w2, ew);

    topk_kernel<<<(M + 255) / 256, 256>>>(ew, masks, M);

    finish_kernel<<<1, 1>>>(tail, M);
}

// round 2
// speedup vs baseline: 1.0002x; 1.0002x over previous
#include <cuda_runtime.h>
#include <math.h>
#include <stdint.h>

typedef unsigned long long ull;

// ---------- f32x2 packed-FMA helpers (Blackwell, PTX-only path) ----------
__device__ __forceinline__ ull dup2(float v) {
    ull r;
    asm("mov.b64 %0, {%1, %1};" : "=l"(r) : "f"(v));
    return r;
}
__device__ __forceinline__ void fma2(ull& d, ull a, ull b) {
    asm("fma.rn.f32x2 %0, %1, %2, %0;" : "+l"(d) : "l"(a), "l"(b));
}
__device__ __forceinline__ void unpack2(ull v, float& lo, float& hi) {
    asm("mov.b64 {%0, %1}, %2;" : "=f"(lo), "=f"(hi) : "l"(v));
}

// ---------- problem constants ----------
#define HDIM 1024      // H
#define NDIM 2048      // 2H
#define NEXP 8
#define BM 64
#define BN 64
#define BK 16
#define NSPLIT 4
#define CHUNKS_PER (NDIM / BN / NSPLIT)   // 8

// scratch for cross-block reductions (no cudaMalloc allowed)
__device__ float g_usage[NEXP];
__device__ int   g_count;

// ---------- kernel 0: init ew = b2 (broadcast), zero scratch ----------
__global__ void init_kernel(float* __restrict__ ew, const float* __restrict__ b2, int n) {
    int i = blockIdx.x * blockDim.x + threadIdx.x;
    if (i < n) ew[i] = b2[i & 7];
    if (blockIdx.x == 0) {
        if (threadIdx.x < NEXP) g_usage[threadIdx.x] = 0.f;
        if (threadIdx.x == 0)   g_count = 0;
    }
}

// ---------- kernel 1: fused  ew += gelu(x@w1 + b1) @ w2  ----------
// block: 256 threads, tx = t&15 (N cols, TN=4), ty = t>>4 (M rows, TM=4)
// grid: (M/BM, NSPLIT); each block handles CHUNKS_PER chunks of 64 N-cols.
__global__ __launch_bounds__(256, 2)
void gemm_kernel(const float* __restrict__ x, const float* __restrict__ w1,
                 const float* __restrict__ b1, const float* __restrict__ w2,
                 float* __restrict__ ew)
{
    __shared__ float xs[BK][BM + 4];     // transposed x tile, pad 4 for store banks
    __shared__ float w1s[BK][BN];
    __shared__ float w2s[BN][9];         // pad to 9 to avoid read conflicts

    const int t  = threadIdx.x;
    const int tx = t & 15;
    const int ty = t >> 4;
    const int mBase = blockIdx.x * BM;

    // x-tile load mapping: one float4 per thread
    const int xr = t >> 2;               // row in tile 0..63
    const int xq = (t & 3) * 4;          // k-offset within BK
    // w1-tile load mapping: one float4 per thread
    const int wk = t >> 4;               // k row 0..15
    const int wn = (t & 15) * 4;         // n col 0..60

    const float* xg = x + (size_t)(mBase + xr) * HDIM + xq;

    float ew_part[4][NEXP];
#pragma unroll
    for (int i = 0; i < 4; ++i)
#pragma unroll
        for (int e = 0; e < NEXP; ++e) ew_part[i][e] = 0.f;

    for (int c = 0; c < CHUNKS_PER; ++c) {
        const int n0 = (blockIdx.y * CHUNKS_PER + c) * BN;

        // load w2 chunk [64 x 8] into padded smem
#pragma unroll
        for (int i = t; i < BN * NEXP; i += 256)
            w2s[i >> 3][i & 7] = w2[(size_t)n0 * NEXP + i];

        // accumulators: rows packed in pairs (f32x2), acc[i2][j]: rows 2*i2, 2*i2+1
        ull acc[2][4];
#pragma unroll
        for (int i2 = 0; i2 < 2; ++i2)
#pragma unroll
            for (int j = 0; j < 4; ++j) acc[i2][j] = 0ULL;

        const float* w1g = w1 + (size_t)wk * NDIM + n0 + wn;

        for (int kt = 0; kt < HDIM / BK; ++kt) {
            // issue global loads early
            float4 xv = *(const float4*)(xg + kt * BK);
            float4 wv = *(const float4*)(w1g + (size_t)kt * BK * NDIM);

            __syncthreads();             // previous tile fully consumed (also covers w2s)
            xs[xq + 0][xr] = xv.x;
            xs[xq + 1][xr] = xv.y;
            xs[xq + 2][xr] = xv.z;
            xs[xq + 3][xr] = xv.w;
            *(float4*)&w1s[wk][wn] = wv;
            __syncthreads();

#pragma unroll
            for (int k = 0; k < BK; ++k) {
                ull a01 = *(const ull*)&xs[k][ty * 4];
                ull a23 = *(const ull*)&xs[k][ty * 4 + 2];
                float4 bv = *(const float4*)&w1s[k][tx * 4];
                ull b0 = dup2(bv.x), b1d = dup2(bv.y), b2d = dup2(bv.z), b3d = dup2(bv.w);
                fma2(acc[0][0], a01, b0);  fma2(acc[1][0], a23, b0);
                fma2(acc[0][1], a01, b1d); fma2(acc[1][1], a23, b1d);
                fma2(acc[0][2], a01, b2d); fma2(acc[1][2], a23, b2d);
                fma2(acc[0][3], a01, b3d); fma2(acc[1][3], a23, b3d);
            }
        }

        // epilogue: +b1, exact GELU, contract with w2 chunk
#pragma unroll
        for (int j = 0; j < 4; ++j) {
            const float bb = __ldg(&b1[n0 + tx * 4 + j]);
            const float* w2row = &w2s[tx * 4 + j][0];
#pragma unroll
            for (int i2 = 0; i2 < 2; ++i2) {
                float vlo, vhi;
                unpack2(acc[i2][j], vlo, vhi);
                float v0 = vlo + bb, v1 = vhi + bb;
                float h0 = 0.5f * v0 * (1.0f + erff(v0 * 0.7071067811865475f));
                float h1 = 0.5f * v1 * (1.0f + erff(v1 * 0.7071067811865475f));
#pragma unroll
                for (int e = 0; e < NEXP; ++e) {
                    float w = w2row[e];
                    ew_part[2 * i2 + 0][e] = fmaf(h0, w, ew_part[2 * i2 + 0][e]);
                    ew_part[2 * i2 + 1][e] = fmaf(h1, w, ew_part[2 * i2 + 1][e]);
                }
            }
        }
        __syncthreads();                 // epilogue done before next w2s overwrite
    }

    // reduce over the 16 tx lanes (xor bits 0..3 stay inside each 16-lane half)
#pragma unroll
    for (int i = 0; i < 4; ++i) {
#pragma unroll
        for (int e = 0; e < NEXP; ++e) {
            float v = ew_part[i][e];
            v += __shfl_xor_sync(0xffffffffu, v, 8);
            v += __shfl_xor_sync(0xffffffffu, v, 4);
            v += __shfl_xor_sync(0xffffffffu, v, 2);
            v += __shfl_xor_sync(0xffffffffu, v, 1);
            if (tx == 0)
                atomicAdd(&ew[(size_t)(mBase + ty * 4 + i) * NEXP + e], v);
        }
    }
}

// ---------- kernel 2: top-2 + softmax + masks + usage reduction ----------
__global__ void topk_kernel(const float* __restrict__ ew, float* __restrict__ masks, int M) {
    __shared__ float susage[NEXP];
    __shared__ int   scount;
    const int t = threadIdx.x;
    if (t < NEXP) susage[t] = 0.f;
    if (t == 0)   scount = 0;
    __syncthreads();

    const int tok = blockIdx.x * blockDim.x + t;
    if (tok < M) {
        float v[NEXP];
        float4 a = *(const float4*)(ew + (size_t)tok * NEXP);
        float4 b = *(const float4*)(ew + (size_t)tok * NEXP + 4);
        v[0] = a.x; v[1] = a.y; v[2] = a.z; v[3] = a.w;
        v[4] = b.x; v[5] = b.y; v[6] = b.z; v[7] = b.w;

        int i1 = 0; float m1 = v[0];
#pragma unroll
        for (int e = 1; e < NEXP; ++e)
            if (v[e] > m1) { m1 = v[e]; i1 = e; }    // strict > : earliest idx on ties (lax.top_k)
        int i2 = -1; float m2 = -3.402823466e38f;
#pragma unroll
        for (int e = 0; e < NEXP; ++e)
            if (e != i1 && v[e] > m2) { m2 = v[e]; i2 = e; }

        float ex = expf(m2 - m1);
        float p1 = 1.f / (1.f + ex);
        float p2 = ex / (1.f + ex);

        float o[NEXP];
#pragma unroll
        for (int e = 0; e < NEXP; ++e)
            o[e] = (e == i1) ? p1 : ((e == i2) ? p2 : 0.f);
        float4 o0 = make_float4(o[0], o[1], o[2], o[3]);
        float4 o1 = make_float4(o[4], o[5], o[6], o[7]);
        *(float4*)(masks + (size_t)tok * NEXP)     = o0;
        *(float4*)(masks + (size_t)tok * NEXP + 4) = o1;

        atomicAdd(&susage[i1], p1);
        atomicAdd(&susage[i2], p2);
        int cnt = (p1 > 0.f) + (p2 > 0.f);
        atomicAdd(&scount, cnt);
    }
    __syncthreads();
    if (t < NEXP) atomicAdd(&g_usage[t], susage[t]);
    if (t == 0)   atomicAdd(&g_count, scount);
}

// ---------- kernel 3: losses + normalized usage ----------
__global__ void finish_kernel(float* __restrict__ tail, int M) {
    float u[NEXP];
    float s = 0.f;
#pragma unroll
    for (int e = 0; e < NEXP; ++e) { u[e] = g_usage[e]; s += u[e]; }
    float lb = 0.f;
#pragma unroll
    for (int e = 0; e < NEXP; ++e) {
        float un = u[e] / s;
        tail[1 + e] = un;                       // expert_usage (normalized)
        float d = un - 0.125f;
        lb += d * d;
    }
    lb *= (1.f / 8.f);                           // mean over E
    float sparsity = ((float)g_count / (float)M) * 0.5f;  // mean(count)/TOP_K
    tail[0] = lb + 0.1f * sparsity;              // total_loss
}

// ---------- launch ----------
extern "C" void kernel_launch(void* const* d_in, const int* in_sizes, int n_in,
                              void* d_out, int out_size) {
    const float* x  = (const float*)d_in[0];
    const float* w1 = (const float*)d_in[1];
    const float* b1 = (const float*)d_in[2];
    const float* w2 = (const float*)d_in[3];
    const float* b2 = (const float*)d_in[4];

    float* out = (float*)d_out;
    const int M = in_sizes[0] / HDIM;            // 16384 tokens

    float* ew    = out;                          // [M, 8]
    float* masks = out + (size_t)M * NEXP;       // [M, 8]
    float* tail  = out + (size_t)2 * M * NEXP;   // [loss, usage x 8]

    init_kernel<<<(M * NEXP + 255) / 256, 256>>>(ew, b2, M * NEXP);

    dim3 grid(M / BM, NSPLIT);
    gemm_kernel<<<grid, 256>>>(x, w1, b1, w2, ew);

    topk_kernel<<<(M + 255) / 256, 256>>>(ew, masks, M);

    finish_kernel<<<1, 1>>>(tail, M);
}

// round 4
// speedup vs baseline: 2.4568x; 2.4562x over previous
#include <cuda_runtime.h>
#include <cuda_fp16.h>
#include <math.h>
#include <stdint.h>

#define HDIM 1024
#define NDIM 2048
#define NEXP 8
#define MTOK 16384
#define BM 128
#define BN 128
#define BK 32
#define KT (HDIM / BK)          // 32

// smem: fp16 tiles, row pitch 40 halfs (80B) -> conflict-free ldmatrix/LDS
#define PITCH 40
#define ST_AH 0
#define ST_AL 10240
#define ST_BH 20480
#define ST_BL 30720
#define STG   40960
#define NSTG  3
#define OFF_W2 (NSTG * STG)             // 122880
#define OFF_B1 (OFF_W2 + BN * NEXP * 4) // 126976
#define SMEM_DYN (OFF_B1 + BN * 4)      // 127488

__device__ __half g_xh[MTOK * HDIM];
__device__ __half g_xl[MTOK * HDIM];
__device__ __half g_wh[NDIM * HDIM];    // w1^T * 1024, hi
__device__ __half g_wl[NDIM * HDIM];    // lo
__device__ float  g_usage[NEXP];
__device__ int    g_count;

// ---------------- PTX helpers ----------------
__device__ __forceinline__ uint32_t smem_u32(const void* p) {
    uint32_t a;
    asm("{ .reg .u64 t; cvta.to.shared.u64 t, %1; cvt.u32.u64 %0, t; }" : "=r"(a) : "l"(p));
    return a;
}
__device__ __forceinline__ void cp16(uint32_t s, const void* g) {
    asm volatile("cp.async.cg.shared.global [%0], [%1], 16;" :: "r"(s), "l"(g));
}
__device__ __forceinline__ void cp_commit() { asm volatile("cp.async.commit_group;" ::: "memory"); }
__device__ __forceinline__ void cp_wait1()  { asm volatile("cp.async.wait_group 1;" ::: "memory"); }
__device__ __forceinline__ void ldm4(uint32_t* r, uint32_t a) {
    asm volatile("ldmatrix.sync.aligned.m8n8.x4.shared.b16 {%0,%1,%2,%3}, [%4];"
                 : "=r"(r[0]), "=r"(r[1]), "=r"(r[2]), "=r"(r[3]) : "r"(a));
}
__device__ __forceinline__ void mma(float* c, const uint32_t* a, const uint32_t* b) {
    asm volatile("mma.sync.aligned.m16n8k16.row.col.f32.f16.f16.f32 "
                 "{%0,%1,%2,%3}, {%4,%5,%6,%7}, {%8,%9}, {%0,%1,%2,%3};"
                 : "+f"(c[0]), "+f"(c[1]), "+f"(c[2]), "+f"(c[3])
                 : "r"(a[0]), "r"(a[1]), "r"(a[2]), "r"(a[3]), "r"(b[0]), "r"(b[1]));
}

// ---------------- kernel 0: convert/transpose + init ----------------
// blocks [0,2048): w1 transpose+scale+split; [2048,18432): x split; rest: ew init
__global__ void pre_kernel(const float* __restrict__ w1, const float* __restrict__ x,
                           float* __restrict__ ew, const float* __restrict__ b2) {
    __shared__ float tile[32][33];
    const int b = blockIdx.x, t = threadIdx.x;
    if (b < 2048) {
        const int nb = (b & 63) * 32, kb = (b >> 6) * 32;
        const int tx = t & 31, ty = t >> 5;
#pragma unroll
        for (int i = 0; i < 4; ++i)
            tile[ty + i * 8][tx] = w1[(size_t)(kb + ty + i * 8) * NDIM + nb + tx];
        __syncthreads();
#pragma unroll
        for (int i = 0; i < 4; ++i) {
            int row = ty + i * 8;
            float v = tile[tx][row] * 1024.0f;
            __half h = __float2half_rn(v);
            __half l = __float2half_rn(v - __half2float(h));
            size_t o = (size_t)(nb + row) * HDIM + kb + tx;
            g_wh[o] = h; g_wl[o] = l;
        }
    } else if (b < 2048 + 16384) {
        const int i = (b - 2048) * 256 + t;          // float4 index
        float4 v = ((const float4*)x)[i];
        __half hx = __float2half_rn(v.x), hy = __float2half_rn(v.y);
        __half hz = __float2half_rn(v.z), hw = __float2half_rn(v.w);
        __half lx = __float2half_rn(v.x - __half2float(hx));
        __half ly = __float2half_rn(v.y - __half2float(hy));
        __half lz = __float2half_rn(v.z - __half2float(hz));
        __half lw = __float2half_rn(v.w - __half2float(hw));
        ((__half2*)g_xh)[i * 2]     = __halves2half2(hx, hy);
        ((__half2*)g_xh)[i * 2 + 1] = __halves2half2(hz, hw);
        ((__half2*)g_xl)[i * 2]     = __halves2half2(lx, ly);
        ((__half2*)g_xl)[i * 2 + 1] = __halves2half2(lz, lw);
    } else {
        const int i = (b - 2048 - 16384) * 256 + t;
        if (i < MTOK * NEXP) ew[i] = b2[i & 7];
        if (b == 2048 + 16384) {
            if (t < NEXP) g_usage[t] = 0.f;
            if (t == 0)   g_count = 0;
        }
    }
}

// ---------------- kernel 1: fused GEMM1 (fp16x3) + GELU + GEMM2 ----------------
__global__ __launch_bounds__(256, 1)
void gemm_kernel(const float* __restrict__ b1, const float* __restrict__ w2,
                 float* __restrict__ ew) {
    extern __shared__ char smem[];
    const uint32_t sb = smem_u32(smem);
    const int t = threadIdx.x, w = t >> 5, lane = t & 31;
    const int wm = w & 3, wn = w >> 2;
    const int n0 = blockIdx.x * BN, m0 = blockIdx.y * BM;

    float* w2s = (float*)(smem + OFF_W2);
    float* b1s = (float*)(smem + OFF_B1);
    for (int i = t; i < BN * NEXP; i += 256) w2s[i] = w2[(size_t)n0 * NEXP + i];
    for (int i = t; i < BN; i += 256)        b1s[i] = b1[n0 + i];

    // cp.async mapping: 2 chunks/thread/buffer; row = t>>1, c16 = (t&1)*2 + j
    const int lrow = t >> 1;
    const size_t ga0 = (size_t)(m0 + lrow) * HDIM;
    const size_t gb0 = (size_t)(n0 + lrow) * HDIM;

#define LOAD_STAGE(stg, kt_)                                                   \
    {                                                                          \
        uint32_t _bs = sb + (stg) * STG + lrow * 80;                           \
        size_t _ka = ga0 + (kt_) * BK;                                         \
        size_t _kb = gb0 + (kt_) * BK;                                         \
        _Pragma("unroll")                                                      \
        for (int j = 0; j < 2; ++j) {                                          \
            int c16 = (t & 1) * 2 + j;                                         \
            uint32_t so = c16 * 16;                                            \
            cp16(_bs + ST_AH + so, g_xh + _ka + c16 * 8);                      \
            cp16(_bs + ST_AL + so, g_xl + _ka + c16 * 8);                      \
            cp16(_bs + ST_BH + so, g_wh + _kb + c16 * 8);                      \
            cp16(_bs + ST_BL + so, g_wl + _kb + c16 * 8);                      \
        }                                                                      \
    }

    LOAD_STAGE(0, 0); cp_commit();
    LOAD_STAGE(1, 1); cp_commit();

    float acc[2][8][4];
#pragma unroll
    for (int mi = 0; mi < 2; ++mi)
#pragma unroll
        for (int ni = 0; ni < 8; ++ni)
#pragma unroll
            for (int c = 0; c < 4; ++c) acc[mi][ni][c] = 0.f;

    // ldmatrix lane row offset (bytes): tiles (m0,k0)(m8,k0)(m0,k8)(m8,k8)
    const uint32_t aoff = ((lane & 7) + ((lane >> 3) & 1) * 8) * 80 + ((lane >> 4) & 1) * 16;
    const uint32_t* s32 = (const uint32_t*)smem;
    const int bword0 = (ST_BH + (wn * 64 + (lane >> 2)) * 80 + (lane & 3) * 4) >> 2;

    for (int kt = 0; kt < KT; ++kt) {
        cp_wait1();
        __syncthreads();
        if (kt + 2 < KT) LOAD_STAGE((kt + 2) % 3, kt + 2);
        cp_commit();

        const uint32_t bs = sb + (kt % 3) * STG;
        const int sw = ((kt % 3) * STG) >> 2;
#pragma unroll
        for (int kk = 0; kk < 2; ++kk) {
            uint32_t ah[2][4], al[2][4];
#pragma unroll
            for (int mi = 0; mi < 2; ++mi) {
                uint32_t ra = bs + ST_AH + (wm * 32 + mi * 16) * 80 + kk * 32 + aoff;
                ldm4(ah[mi], ra);
                ldm4(al[mi], ra + (ST_AL - ST_AH));
            }
#pragma unroll
            for (int ni = 0; ni < 8; ++ni) {
                int bo = sw + bword0 + (ni * 8 * 80 + kk * 32) / 4;
                uint32_t bh[2], bl[2];
                bh[0] = s32[bo];                         bh[1] = s32[bo + 4];
                bl[0] = s32[bo + (ST_BL - ST_BH) / 4];   bl[1] = s32[bo + (ST_BL - ST_BH) / 4 + 4];
#pragma unroll
                for (int mi = 0; mi < 2; ++mi) {
                    mma(acc[mi][ni], ah[mi], bh);
                    mma(acc[mi][ni], ah[mi], bl);
                    mma(acc[mi][ni], al[mi], bh);
                }
            }
        }
    }

    // epilogue: v = acc/1024 + b1 -> exact gelu -> x w2 -> partials
    float part[4][NEXP];
#pragma unroll
    for (int p = 0; p < 4; ++p)
#pragma unroll
        for (int e = 0; e < NEXP; ++e) part[p][e] = 0.f;

    const float isc = 1.0f / 1024.0f;
#pragma unroll
    for (int mi = 0; mi < 2; ++mi)
#pragma unroll
        for (int h = 0; h < 2; ++h) {
            const int pi = mi * 2 + h;
#pragma unroll
            for (int ni = 0; ni < 8; ++ni) {
                int nl = wn * 64 + ni * 8 + (lane & 3) * 2;
                float v0 = acc[mi][ni][h * 2 + 0] * isc + b1s[nl];
                float v1 = acc[mi][ni][h * 2 + 1] * isc + b1s[nl + 1];
                float g0 = 0.5f * v0 * (1.0f + erff(v0 * 0.7071067811865475f));
                float g1 = 0.5f * v1 * (1.0f + erff(v1 * 0.7071067811865475f));
                const float* wr = w2s + nl * NEXP;
#pragma unroll
                for (int e = 0; e < NEXP; ++e)
                    part[pi][e] = fmaf(g0, wr[e], fmaf(g1, wr[NEXP + e], part[pi][e]));
            }
        }
#pragma unroll
    for (int p = 0; p < 4; ++p)
#pragma unroll
        for (int e = 0; e < NEXP; ++e) {
            float v = part[p][e];
            v += __shfl_xor_sync(0xffffffffu, v, 1);
            v += __shfl_xor_sync(0xffffffffu, v, 2);
            part[p][e] = v;
        }
    if ((lane & 3) == 0) {
#pragma unroll
        for (int p = 0; p < 4; ++p) {
            int r = m0 + wm * 32 + (p >> 1) * 16 + (p & 1) * 8 + (lane >> 2);
#pragma unroll
            for (int e = 0; e < NEXP; ++e)
                atomicAdd(&ew[(size_t)r * NEXP + e], part[p][e]);
        }
    }
}

// ---------------- kernel 2: top-2 + softmax + masks + usage ----------------
__global__ void topk_kernel(const float* __restrict__ ew, float* __restrict__ masks, int M) {
    __shared__ float su[NEXP];
    __shared__ int sc;
    const int t = threadIdx.x;
    if (t < NEXP) su[t] = 0.f;
    if (t == 0)   sc = 0;
    __syncthreads();
    const int tok = blockIdx.x * blockDim.x + t;
    if (tok < M) {
        float v[NEXP];
        float4 a = *(const float4*)(ew + (size_t)tok * NEXP);
        float4 b = *(const float4*)(ew + (size_t)tok * NEXP + 4);
        v[0]=a.x; v[1]=a.y; v[2]=a.z; v[3]=a.w; v[4]=b.x; v[5]=b.y; v[6]=b.z; v[7]=b.w;
        int i1 = 0; float m1 = v[0];
#pragma unroll
        for (int e = 1; e < NEXP; ++e) if (v[e] > m1) { m1 = v[e]; i1 = e; }
        int i2 = -1; float m2 = -3.402823466e38f;
#pragma unroll
        for (int e = 0; e < NEXP; ++e) if (e != i1 && v[e] > m2) { m2 = v[e]; i2 = e; }
        float ex = expf(m2 - m1);
        float p1 = 1.f / (1.f + ex), p2 = ex / (1.f + ex);
        float o[NEXP];
#pragma unroll
        for (int e = 0; e < NEXP; ++e) o[e] = (e == i1) ? p1 : ((e == i2) ? p2 : 0.f);
        *(float4*)(masks + (size_t)tok * NEXP)     = make_float4(o[0], o[1], o[2], o[3]);
        *(float4*)(masks + (size_t)tok * NEXP + 4) = make_float4(o[4], o[5], o[6], o[7]);
        atomicAdd(&su[i1], p1);
        atomicAdd(&su[i2], p2);
        atomicAdd(&sc, (p1 > 0.f) + (p2 > 0.f));
    }
    __syncthreads();
    if (t < NEXP) atomicAdd(&g_usage[t], su[t]);
    if (t == 0)   atomicAdd(&g_count, sc);
}

// ---------------- kernel 3: losses ----------------
__global__ void finish_kernel(float* __restrict__ tail, int M) {
    float u[NEXP], s = 0.f;
#pragma unroll
    for (int e = 0; e < NEXP; ++e) { u[e] = g_usage[e]; s += u[e]; }
    float lb = 0.f;
#pragma unroll
    for (int e = 0; e < NEXP; ++e) {
        float un = u[e] / s;
        tail[1 + e] = un;
        float d = un - 0.125f;
        lb += d * d;
    }
    lb *= (1.f / 8.f);
    float sp = ((float)g_count / (float)M) * 0.5f;
    tail[0] = lb + 0.1f * sp;
}

// ---------------- launch ----------------
extern "C" void kernel_launch(void* const* d_in, const int* in_sizes, int n_in,
                              void* d_out, int out_size) {
    const float* x  = (const float*)d_in[0];
    const float* w1 = (const float*)d_in[1];
    const float* b1 = (const float*)d_in[2];
    const float* w2 = (const float*)d_in[3];
    const float* b2 = (const float*)d_in[4];

    float* out   = (float*)d_out;
    const int M  = in_sizes[0] / HDIM;            // 16384
    float* ew    = out;
    float* masks = out + (size_t)M * NEXP;
    float* tail  = out + (size_t)2 * M * NEXP;

    cudaFuncSetAttribute(gemm_kernel, cudaFuncAttributeMaxDynamicSharedMemorySize, SMEM_DYN);

    const int initBlocks = (M * NEXP + 255) / 256;
    pre_kernel<<<2048 + 16384 + initBlocks, 256>>>(w1, x, ew, b2);
    gemm_kernel<<<dim3(NDIM / BN, M / BM), 256, SMEM_DYN>>>(b1, w2, ew);
    topk_kernel<<<(M + 255) / 256, 256>>>(ew, masks, M);
    finish_kernel<<<1, 1>>>(tail, M);
}

// round 5
// speedup vs baseline: 2.7253x; 1.1093x over previous
#include <cuda_runtime.h>
#include <cuda_fp16.h>
#include <math.h>
#include <stdint.h>

#define HDIM 1024
#define NDIM 2048
#define NEXP 8
#define MTOK 16384
#define BM 128
#define BN 128
#define BK 32
#define KT (HDIM / BK)          // 32

// smem: fp16 tiles, row pitch 40 halfs (80B) -> conflict-free ldmatrix/LDS
#define ST_AH 0
#define ST_AL 10240
#define ST_BH 20480
#define ST_BL 30720
#define STG   40960
#define NSTG  2
#define OFF_W2 (NSTG * STG)             // 81920
#define OFF_B1 (OFF_W2 + BN * NEXP * 4) // 86016
#define SMEM_DYN (OFF_B1 + BN * 4)      // 86528  (x2 CTAs = 173KB <= 228KB)

__device__ __half g_wh[NDIM * HDIM];    // w1^T * 1024, hi
__device__ __half g_wl[NDIM * HDIM];    // lo
__device__ float  g_usage[NEXP];
__device__ int    g_count;
__device__ int    g_done;

// ---------------- PTX helpers ----------------
__device__ __forceinline__ uint32_t smem_u32(const void* p) {
    uint32_t a;
    asm("{ .reg .u64 t; cvta.to.shared.u64 t, %1; cvt.u32.u64 %0, t; }" : "=r"(a) : "l"(p));
    return a;
}
__device__ __forceinline__ void cp16(uint32_t s, const void* g) {
    asm volatile("cp.async.cg.shared.global [%0], [%1], 16;" :: "r"(s), "l"(g));
}
__device__ __forceinline__ void cp_commit() { asm volatile("cp.async.commit_group;" ::: "memory"); }
__device__ __forceinline__ void cp_wait0()  { asm volatile("cp.async.wait_group 0;" ::: "memory"); }
__device__ __forceinline__ void ldm4(uint32_t* r, uint32_t a) {
    asm volatile("ldmatrix.sync.aligned.m8n8.x4.shared.b16 {%0,%1,%2,%3}, [%4];"
                 : "=r"(r[0]), "=r"(r[1]), "=r"(r[2]), "=r"(r[3]) : "r"(a));
}
__device__ __forceinline__ void mma(float* c, const uint32_t* a, const uint32_t* b) {
    asm volatile("mma.sync.aligned.m16n8k16.row.col.f32.f16.f16.f32 "
                 "{%0,%1,%2,%3}, {%4,%5,%6,%7}, {%8,%9}, {%0,%1,%2,%3};"
                 : "+f"(c[0]), "+f"(c[1]), "+f"(c[2]), "+f"(c[3])
                 : "r"(a[0]), "r"(a[1]), "r"(a[2]), "r"(a[3]), "r"(b[0]), "r"(b[1]));
}
// pack two floats -> hi half2 (as u32) and lo-residual half2 (as u32)
__device__ __forceinline__ void split2(float a, float b, uint32_t& H, uint32_t& L) {
    __half ha = __float2half_rn(a), hb = __float2half_rn(b);
    __half la = __float2half_rn(a - __half2float(ha));
    __half lb = __float2half_rn(b - __half2float(hb));
    __half2 h2 = __halves2half2(ha, hb), l2 = __halves2half2(la, lb);
    H = *(uint32_t*)&h2; L = *(uint32_t*)&l2;
}

// ---------------- kernel 0: w1 transpose+scale+split + init ----------------
__global__ void pre_kernel(const float* __restrict__ w1, float* __restrict__ ew,
                           const float* __restrict__ b2) {
    __shared__ float tile[32][33];
    const int b = blockIdx.x, t = threadIdx.x;
    if (b < 2048) {
        const int nb = (b & 63) * 32, kb = (b >> 6) * 32;
        const int tx = t & 31, ty = t >> 5;
#pragma unroll
        for (int i = 0; i < 4; ++i)
            tile[ty + i * 8][tx] = w1[(size_t)(kb + ty + i * 8) * NDIM + nb + tx];
        __syncthreads();
#pragma unroll
        for (int i = 0; i < 4; ++i) {
            int row = ty + i * 8;
            float v = tile[tx][row] * 1024.0f;
            __half h = __float2half_rn(v);
            __half l = __float2half_rn(v - __half2float(h));
            size_t o = (size_t)(nb + row) * HDIM + kb + tx;
            g_wh[o] = h; g_wl[o] = l;
        }
    } else {
        const int i = (b - 2048) * 256 + t;
        if (i < MTOK * NEXP) ew[i] = b2[i & 7];
        if (b == 2048) {
            if (t < NEXP) g_usage[t] = 0.f;
            if (t == 0) { g_count = 0; g_done = 0; }
        }
    }
}

// ---------------- kernel 1: fused GEMM1 (fp16x3) + GELU + GEMM2 ----------------
__global__ __launch_bounds__(256, 2)
void gemm_kernel(const float* __restrict__ x, const float* __restrict__ b1,
                 const float* __restrict__ w2, float* __restrict__ ew) {
    extern __shared__ char smem[];
    const uint32_t sb = smem_u32(smem);
    const int t = threadIdx.x, w = t >> 5, lane = t & 31;
    const int wm = w & 3, wn = w >> 2;
    const int n0 = blockIdx.x * BN, m0 = blockIdx.y * BM;

    float* w2s = (float*)(smem + OFF_W2);
    float* b1s = (float*)(smem + OFF_B1);
    for (int i = t; i < BN * NEXP; i += 256) w2s[i] = w2[(size_t)n0 * NEXP + i];
    for (int i = t; i < BN; i += 256)        b1s[i] = b1[n0 + i];

    // A on-the-fly: thread t owns row t>>1, 16 fp32 cols at (t&1)*16
    const float* xg = x + (size_t)(m0 + (t >> 1)) * HDIM + (t & 1) * 16;
    const uint32_t aDst = sb + ST_AH + (t >> 1) * 80 + (t & 1) * 32;

    // B via cp.async: thread t -> row t>>1, two 16B chunks
    const int lrow = t >> 1;
    const size_t gb0 = (size_t)(n0 + lrow) * HDIM;

#define LOAD_B(stg, kt_)                                                       \
    {                                                                          \
        uint32_t _bs = sb + (stg) * STG + lrow * 80;                           \
        size_t _kb = gb0 + (size_t)(kt_) * BK;                                 \
        _Pragma("unroll")                                                      \
        for (int j = 0; j < 2; ++j) {                                          \
            int c16 = (t & 1) * 2 + j;                                         \
            uint32_t so = c16 * 16;                                            \
            cp16(_bs + ST_BH + so, g_wh + _kb + c16 * 8);                      \
            cp16(_bs + ST_BL + so, g_wl + _kb + c16 * 8);                      \
        }                                                                      \
    }

#define STS_A(stg, ra)                                                         \
    {                                                                          \
        uint4 H, L;                                                            \
        split2((ra)[0].x, (ra)[0].y, H.x, L.x);                                \
        split2((ra)[0].z, (ra)[0].w, H.y, L.y);                                \
        split2((ra)[1].x, (ra)[1].y, H.z, L.z);                                \
        split2((ra)[1].z, (ra)[1].w, H.w, L.w);                                \
        *(uint4*)(smem + (aDst - sb) + (stg) * STG) = H;                       \
        *(uint4*)(smem + (aDst - sb) + (stg) * STG + (ST_AL - ST_AH)) = L;     \
        split2((ra)[2].x, (ra)[2].y, H.x, L.x);                                \
        split2((ra)[2].z, (ra)[2].w, H.y, L.y);                                \
        split2((ra)[3].x, (ra)[3].y, H.z, L.z);                                \
        split2((ra)[3].z, (ra)[3].w, H.w, L.w);                                \
        *(uint4*)(smem + (aDst - sb) + (stg) * STG + 16) = H;                  \
        *(uint4*)(smem + (aDst - sb) + (stg) * STG + (ST_AL - ST_AH) + 16) = L;\
    }

    float4 ra[4];
    // prologue: A(0) -> regs -> smem stage 0; B(0) via cp.async; prefetch A(1)
#pragma unroll
    for (int i = 0; i < 4; ++i) ra[i] = *(const float4*)(xg + 4 * i);
    LOAD_B(0, 0); cp_commit();
    STS_A(0, ra);
#pragma unroll
    for (int i = 0; i < 4; ++i) ra[i] = *(const float4*)(xg + BK + 4 * i);

    float acc[2][8][4];
#pragma unroll
    for (int mi = 0; mi < 2; ++mi)
#pragma unroll
        for (int ni = 0; ni < 8; ++ni)
#pragma unroll
            for (int c = 0; c < 4; ++c) acc[mi][ni][c] = 0.f;

    const uint32_t aoff = ((lane & 7) + ((lane >> 3) & 1) * 8) * 80 + ((lane >> 4) & 1) * 16;
    const uint32_t* s32 = (const uint32_t*)smem;
    const int bword0 = (ST_BH + (wn * 64 + (lane >> 2)) * 80 + (lane & 3) * 4) >> 2;

    for (int kt = 0; kt < KT; ++kt) {
        cp_wait0();              // B(kt) landed (issued one full iter ago)
        __syncthreads();         // + A(kt) STS visible, prev stage reads done
        if (kt + 1 < KT) {
            LOAD_B((kt + 1) & 1, kt + 1); cp_commit();
            STS_A((kt + 1) & 1, ra);
        }
        if (kt + 2 < KT) {
#pragma unroll
            for (int i = 0; i < 4; ++i) ra[i] = *(const float4*)(xg + (kt + 2) * BK + 4 * i);
        }

        const uint32_t bs = sb + (kt & 1) * STG;
        const int sw = ((kt & 1) * STG) >> 2;
#pragma unroll
        for (int kk = 0; kk < 2; ++kk) {
            uint32_t ah[2][4], al[2][4];
#pragma unroll
            for (int mi = 0; mi < 2; ++mi) {
                uint32_t raddr = bs + ST_AH + (wm * 32 + mi * 16) * 80 + kk * 32 + aoff;
                ldm4(ah[mi], raddr);
                ldm4(al[mi], raddr + (ST_AL - ST_AH));
            }
#pragma unroll
            for (int ni = 0; ni < 8; ++ni) {
                int bo = sw + bword0 + (ni * 8 * 80 + kk * 32) / 4;
                uint32_t bh[2], bl[2];
                bh[0] = s32[bo];                         bh[1] = s32[bo + 4];
                bl[0] = s32[bo + (ST_BL - ST_BH) / 4];   bl[1] = s32[bo + (ST_BL - ST_BH) / 4 + 4];
#pragma unroll
                for (int mi = 0; mi < 2; ++mi) {
                    mma(acc[mi][ni], ah[mi], bh);
                    mma(acc[mi][ni], ah[mi], bl);
                    mma(acc[mi][ni], al[mi], bh);
                }
            }
        }
    }

    // epilogue: v = acc/1024 + b1 -> exact gelu -> x w2 -> partials
    float part[4][NEXP];
#pragma unroll
    for (int p = 0; p < 4; ++p)
#pragma unroll
        for (int e = 0; e < NEXP; ++e) part[p][e] = 0.f;

    const float isc = 1.0f / 1024.0f;
#pragma unroll
    for (int mi = 0; mi < 2; ++mi)
#pragma unroll
        for (int h = 0; h < 2; ++h) {
            const int pi = mi * 2 + h;
#pragma unroll
            for (int ni = 0; ni < 8; ++ni) {
                int nl = wn * 64 + ni * 8 + (lane & 3) * 2;
                float v0 = acc[mi][ni][h * 2 + 0] * isc + b1s[nl];
                float v1 = acc[mi][ni][h * 2 + 1] * isc + b1s[nl + 1];
                float g0 = 0.5f * v0 * (1.0f + erff(v0 * 0.7071067811865475f));
                float g1 = 0.5f * v1 * (1.0f + erff(v1 * 0.7071067811865475f));
                const float* wr = w2s + nl * NEXP;
#pragma unroll
                for (int e = 0; e < NEXP; ++e)
                    part[pi][e] = fmaf(g0, wr[e], fmaf(g1, wr[NEXP + e], part[pi][e]));
            }
        }
#pragma unroll
    for (int p = 0; p < 4; ++p)
#pragma unroll
        for (int e = 0; e < NEXP; ++e) {
            float v = part[p][e];
            v += __shfl_xor_sync(0xffffffffu, v, 1);
            v += __shfl_xor_sync(0xffffffffu, v, 2);
            part[p][e] = v;
        }
    if ((lane & 3) == 0) {
#pragma unroll
        for (int p = 0; p < 4; ++p) {
            int r = m0 + wm * 32 + (p >> 1) * 16 + (p & 1) * 8 + (lane >> 2);
#pragma unroll
            for (int e = 0; e < NEXP; ++e)
                atomicAdd(&ew[(size_t)r * NEXP + e], part[p][e]);
        }
    }
}

// ---------------- kernel 2: top-2 + softmax + masks + usage + (last block) losses ----
__global__ void topk_kernel(const float* __restrict__ ew, float* __restrict__ masks,
                            float* __restrict__ tail, int M) {
    __shared__ float su[NEXP];
    __shared__ int sc;
    const int t = threadIdx.x;
    if (t < NEXP) su[t] = 0.f;
    if (t == 0)   sc = 0;
    __syncthreads();
    const int tok = blockIdx.x * blockDim.x + t;
    if (tok < M) {
        float v[NEXP];
        float4 a = *(const float4*)(ew + (size_t)tok * NEXP);
        float4 b = *(const float4*)(ew + (size_t)tok * NEXP + 4);
        v[0]=a.x; v[1]=a.y; v[2]=a.z; v[3]=a.w; v[4]=b.x; v[5]=b.y; v[6]=b.z; v[7]=b.w;
        int i1 = 0; float m1 = v[0];
#pragma unroll
        for (int e = 1; e < NEXP; ++e) if (v[e] > m1) { m1 = v[e]; i1 = e; }
        int i2 = -1; float m2 = -3.402823466e38f;
#pragma unroll
        for (int e = 0; e < NEXP; ++e) if (e != i1 && v[e] > m2) { m2 = v[e]; i2 = e; }
        float ex = expf(m2 - m1);
        float p1 = 1.f / (1.f + ex), p2 = ex / (1.f + ex);
        float o[NEXP];
#pragma unroll
        for (int e = 0; e < NEXP; ++e) o[e] = (e == i1) ? p1 : ((e == i2) ? p2 : 0.f);
        *(float4*)(masks + (size_t)tok * NEXP)     = make_float4(o[0], o[1], o[2], o[3]);
        *(float4*)(masks + (size_t)tok * NEXP + 4) = make_float4(o[4], o[5], o[6], o[7]);
        atomicAdd(&su[i1], p1);
        atomicAdd(&su[i2], p2);
        atomicAdd(&sc, (p1 > 0.f) + (p2 > 0.f));
    }
    __syncthreads();
    if (t < NEXP) atomicAdd(&g_usage[t], su[t]);
    if (t == 0)   atomicAdd(&g_count, sc);
    __threadfence();
    __syncthreads();
    if (t == 0 && atomicAdd(&g_done, 1) == (int)gridDim.x - 1) {
        __threadfence();
        float u[NEXP], s = 0.f;
#pragma unroll
        for (int e = 0; e < NEXP; ++e) { u[e] = g_usage[e]; s += u[e]; }
        float lb = 0.f;
#pragma unroll
        for (int e = 0; e < NEXP; ++e) {
            float un = u[e] / s;
            tail[1 + e] = un;
            float d = un - 0.125f;
            lb += d * d;
        }
        lb *= (1.f / 8.f);
        float sp = ((float)g_count / (float)M) * 0.5f;
        tail[0] = lb + 0.1f * sp;
    }
}

// ---------------- launch ----------------
extern "C" void kernel_launch(void* const* d_in, const int* in_sizes, int n_in,
                              void* d_out, int out_size) {
    const float* x  = (const float*)d_in[0];
    const float* w1 = (const float*)d_in[1];
    const float* b1 = (const float*)d_in[2];
    const float* w2 = (const float*)d_in[3];
    const float* b2 = (const float*)d_in[4];

    float* out   = (float*)d_out;
    const int M  = in_sizes[0] / HDIM;            // 16384
    float* ew    = out;
    float* masks = out + (size_t)M * NEXP;
    float* tail  = out + (size_t)2 * M * NEXP;

    cudaFuncSetAttribute(gemm_kernel, cudaFuncAttributeMaxDynamicSharedMemorySize, SMEM_DYN);

    pre_kernel<<<2048 + (M * NEXP + 255) / 256, 256>>>(w1, ew, b2);
    gemm_kernel<<<dim3(NDIM / BN, M / BM), 256, SMEM_DYN>>>(x, b1, w2, ew);
    topk_kernel<<<(M + 255) / 256, 256>>>(ew, masks, tail, M);
}

// round 6
// speedup vs baseline: 2.7262x; 1.0004x over previous
#include <cuda_runtime.h>
#include <cuda_fp16.h>
#include <math.h>
#include <stdint.h>

#define HDIM 1024
#define NDIM 2048
#define NEXP 8
#define MTOK 16384
#define BM 128
#define BN 128
#define BK 32
#define KT (HDIM / BK)          // 32

// smem: fp16 tiles, row pitch 40 halfs (80B) -> conflict-free ldmatrix/LDS
#define ST_AH 0
#define ST_AL 10240
#define ST_BH 20480
#define ST_BL 30720
#define STG   40960
#define NSTG  2
#define OFF_W2 (NSTG * STG)             // 81920
#define OFF_B1 (OFF_W2 + BN * NEXP * 4) // 86016
#define SMEM_DYN (OFF_B1 + BN * 4)      // 86528  (x2 CTAs = 173KB <= 228KB)

__device__ __half g_wh[NDIM * HDIM];    // w1^T * 1024, hi
__device__ __half g_wl[NDIM * HDIM];    // lo
__device__ float  g_usage[NEXP];
__device__ int    g_count;
__device__ int    g_done;

// ---------------- PTX helpers ----------------
__device__ __forceinline__ uint32_t smem_u32(const void* p) {
    uint32_t a;
    asm("{ .reg .u64 t; cvta.to.shared.u64 t, %1; cvt.u32.u64 %0, t; }" : "=r"(a) : "l"(p));
    return a;
}
__device__ __forceinline__ void cp16(uint32_t s, const void* g) {
    asm volatile("cp.async.cg.shared.global [%0], [%1], 16;" :: "r"(s), "l"(g));
}
__device__ __forceinline__ void cp_commit() { asm volatile("cp.async.commit_group;" ::: "memory"); }
__device__ __forceinline__ void cp_wait0()  { asm volatile("cp.async.wait_group 0;" ::: "memory"); }
__device__ __forceinline__ void ldm4(uint32_t* r, uint32_t a) {
    asm volatile("ldmatrix.sync.aligned.m8n8.x4.shared.b16 {%0,%1,%2,%3}, [%4];"
                 : "=r"(r[0]), "=r"(r[1]), "=r"(r[2]), "=r"(r[3]) : "r"(a));
}
__device__ __forceinline__ void mma(float* c, const uint32_t* a, const uint32_t* b) {
    asm volatile("mma.sync.aligned.m16n8k16.row.col.f32.f16.f16.f32 "
                 "{%0,%1,%2,%3}, {%4,%5,%6,%7}, {%8,%9}, {%0,%1,%2,%3};"
                 : "+f"(c[0]), "+f"(c[1]), "+f"(c[2]), "+f"(c[3])
                 : "r"(a[0]), "r"(a[1]), "r"(a[2]), "r"(a[3]), "r"(b[0]), "r"(b[1]));
}
// pack two floats -> hi half2 (as u32) and lo-residual half2 (as u32)
__device__ __forceinline__ void split2(float a, float b, uint32_t& H, uint32_t& L) {
    __half ha = __float2half_rn(a), hb = __float2half_rn(b);
    __half la = __float2half_rn(a - __half2float(ha));
    __half lb = __float2half_rn(b - __half2float(hb));
    __half2 h2 = __halves2half2(ha, hb), l2 = __halves2half2(la, lb);
    H = *(uint32_t*)&h2; L = *(uint32_t*)&l2;
}

// ---------------- kernel 0: w1 transpose+scale+split + init ----------------
__global__ void pre_kernel(const float* __restrict__ w1, float* __restrict__ ew,
                           const float* __restrict__ b2) {
    __shared__ float tile[32][33];
    const int b = blockIdx.x, t = threadIdx.x;
    if (b < 2048) {
        const int nb = (b & 63) * 32, kb = (b >> 6) * 32;
        const int tx = t & 31, ty = t >> 5;
#pragma unroll
        for (int i = 0; i < 4; ++i)
            tile[ty + i * 8][tx] = w1[(size_t)(kb + ty + i * 8) * NDIM + nb + tx];
        __syncthreads();
#pragma unroll
        for (int i = 0; i < 4; ++i) {
            int row = ty + i * 8;
            float v = tile[tx][row] * 1024.0f;
            __half h = __float2half_rn(v);
            __half l = __float2half_rn(v - __half2float(h));
            size_t o = (size_t)(nb + row) * HDIM + kb + tx;
            g_wh[o] = h; g_wl[o] = l;
        }
    } else {
        const int i = (b - 2048) * 256 + t;
        if (i < MTOK * NEXP) ew[i] = b2[i & 7];
        if (b == 2048) {
            if (t < NEXP) g_usage[t] = 0.f;
            if (t == 0) { g_count = 0; g_done = 0; }
        }
    }
}

// ---------------- kernel 1: fused GEMM1 (fp16x3) + GELU + GEMM2 ----------------
__global__ __launch_bounds__(256, 2)
void gemm_kernel(const float* __restrict__ x, const float* __restrict__ b1,
                 const float* __restrict__ w2, float* __restrict__ ew) {
    extern __shared__ char smem[];
    const uint32_t sb = smem_u32(smem);
    const int t = threadIdx.x, w = t >> 5, lane = t & 31;
    const int wm = w & 3, wn = w >> 2;
    const int n0 = blockIdx.x * BN, m0 = blockIdx.y * BM;

    float* w2s = (float*)(smem + OFF_W2);
    float* b1s = (float*)(smem + OFF_B1);
    for (int i = t; i < BN * NEXP; i += 256) w2s[i] = w2[(size_t)n0 * NEXP + i];
    for (int i = t; i < BN; i += 256)        b1s[i] = b1[n0 + i];

    // A on-the-fly: thread t owns row t>>1, 16 fp32 cols at (t&1)*16
    const float* xg = x + (size_t)(m0 + (t >> 1)) * HDIM + (t & 1) * 16;
    const uint32_t aDst = sb + ST_AH + (t >> 1) * 80 + (t & 1) * 32;

    // B via cp.async: thread t -> row t>>1, two 16B chunks
    const int lrow = t >> 1;
    const size_t gb0 = (size_t)(n0 + lrow) * HDIM;

#define LOAD_B(stg, kt_)                                                       \
    {                                                                          \
        uint32_t _bs = sb + (stg) * STG + lrow * 80;                           \
        size_t _kb = gb0 + (size_t)(kt_) * BK;                                 \
        _Pragma("unroll")                                                      \
        for (int j = 0; j < 2; ++j) {                                          \
            int c16 = (t & 1) * 2 + j;                                         \
            uint32_t so = c16 * 16;                                            \
            cp16(_bs + ST_BH + so, g_wh + _kb + c16 * 8);                      \
            cp16(_bs + ST_BL + so, g_wl + _kb + c16 * 8);                      \
        }                                                                      \
    }

#define STS_A(stg, ra)                                                         \
    {                                                                          \
        uint4 H, L;                                                            \
        split2((ra)[0].x, (ra)[0].y, H.x, L.x);                                \
        split2((ra)[0].z, (ra)[0].w, H.y, L.y);                                \
        split2((ra)[1].x, (ra)[1].y, H.z, L.z);                                \
        split2((ra)[1].z, (ra)[1].w, H.w, L.w);                                \
        *(uint4*)(smem + (aDst - sb) + (stg) * STG) = H;                       \
        *(uint4*)(smem + (aDst - sb) + (stg) * STG + (ST_AL - ST_AH)) = L;     \
        split2((ra)[2].x, (ra)[2].y, H.x, L.x);                                \
        split2((ra)[2].z, (ra)[2].w, H.y, L.y);                                \
        split2((ra)[3].x, (ra)[3].y, H.z, L.z);                                \
        split2((ra)[3].z, (ra)[3].w, H.w, L.w);                                \
        *(uint4*)(smem + (aDst - sb) + (stg) * STG + 16) = H;                  \
        *(uint4*)(smem + (aDst - sb) + (stg) * STG + (ST_AL - ST_AH) + 16) = L;\
    }

    float4 ra[4];
    // prologue: A(0) -> regs -> smem stage 0; B(0) via cp.async; prefetch A(1)
#pragma unroll
    for (int i = 0; i < 4; ++i) ra[i] = *(const float4*)(xg + 4 * i);
    LOAD_B(0, 0); cp_commit();
    STS_A(0, ra);
#pragma unroll
    for (int i = 0; i < 4; ++i) ra[i] = *(const float4*)(xg + BK + 4 * i);

    float acc[2][8][4];
#pragma unroll
    for (int mi = 0; mi < 2; ++mi)
#pragma unroll
        for (int ni = 0; ni < 8; ++ni)
#pragma unroll
            for (int c = 0; c < 4; ++c) acc[mi][ni][c] = 0.f;

    const uint32_t aoff = ((lane & 7) + ((lane >> 3) & 1) * 8) * 80 + ((lane >> 4) & 1) * 16;
    const uint32_t* s32 = (const uint32_t*)smem;
    const int bword0 = (ST_BH + (wn * 64 + (lane >> 2)) * 80 + (lane & 3) * 4) >> 2;

    for (int kt = 0; kt < KT; ++kt) {
        cp_wait0();              // B(kt) landed (issued one full iter ago)
        __syncthreads();         // + A(kt) STS visible, prev stage reads done
        if (kt + 1 < KT) {
            LOAD_B((kt + 1) & 1, kt + 1); cp_commit();
            STS_A((kt + 1) & 1, ra);
        }
        if (kt + 2 < KT) {
#pragma unroll
            for (int i = 0; i < 4; ++i) ra[i] = *(const float4*)(xg + (kt + 2) * BK + 4 * i);
        }

        const uint32_t bs = sb + (kt & 1) * STG;
        const int sw = ((kt & 1) * STG) >> 2;
#pragma unroll
        for (int kk = 0; kk < 2; ++kk) {
            uint32_t ah[2][4], al[2][4];
#pragma unroll
            for (int mi = 0; mi < 2; ++mi) {
                uint32_t raddr = bs + ST_AH + (wm * 32 + mi * 16) * 80 + kk * 32 + aoff;
                ldm4(ah[mi], raddr);
                ldm4(al[mi], raddr + (ST_AL - ST_AH));
            }
#pragma unroll
            for (int ni = 0; ni < 8; ++ni) {
                int bo = sw + bword0 + (ni * 8 * 80 + kk * 32) / 4;
                uint32_t bh[2], bl[2];
                bh[0] = s32[bo];                         bh[1] = s32[bo + 4];
                bl[0] = s32[bo + (ST_BL - ST_BH) / 4];   bl[1] = s32[bo + (ST_BL - ST_BH) / 4 + 4];
#pragma unroll
                for (int mi = 0; mi < 2; ++mi) {
                    mma(acc[mi][ni], ah[mi], bh);
                    mma(acc[mi][ni], ah[mi], bl);
                    mma(acc[mi][ni], al[mi], bh);
                }
            }
        }
    }

    // epilogue: v = acc/1024 + b1 -> exact gelu -> x w2 -> partials
    float part[4][NEXP];
#pragma unroll
    for (int p = 0; p < 4; ++p)
#pragma unroll
        for (int e = 0; e < NEXP; ++e) part[p][e] = 0.f;

    const float isc = 1.0f / 1024.0f;
#pragma unroll
    for (int mi = 0; mi < 2; ++mi)
#pragma unroll
        for (int h = 0; h < 2; ++h) {
            const int pi = mi * 2 + h;
#pragma unroll
            for (int ni = 0; ni < 8; ++ni) {
                int nl = wn * 64 + ni * 8 + (lane & 3) * 2;
                float v0 = acc[mi][ni][h * 2 + 0] * isc + b1s[nl];
                float v1 = acc[mi][ni][h * 2 + 1] * isc + b1s[nl + 1];
                float g0 = 0.5f * v0 * (1.0f + erff(v0 * 0.7071067811865475f));
                float g1 = 0.5f * v1 * (1.0f + erff(v1 * 0.7071067811865475f));
                const float* wr = w2s + nl * NEXP;
#pragma unroll
                for (int e = 0; e < NEXP; ++e)
                    part[pi][e] = fmaf(g0, wr[e], fmaf(g1, wr[NEXP + e], part[pi][e]));
            }
        }
#pragma unroll
    for (int p = 0; p < 4; ++p)
#pragma unroll
        for (int e = 0; e < NEXP; ++e) {
            float v = part[p][e];
            v += __shfl_xor_sync(0xffffffffu, v, 1);
            v += __shfl_xor_sync(0xffffffffu, v, 2);
            part[p][e] = v;
        }
    if ((lane & 3) == 0) {
#pragma unroll
        for (int p = 0; p < 4; ++p) {
            int r = m0 + wm * 32 + (p >> 1) * 16 + (p & 1) * 8 + (lane >> 2);
#pragma unroll
            for (int e = 0; e < NEXP; ++e)
                atomicAdd(&ew[(size_t)r * NEXP + e], part[p][e]);
        }
    }
}

// ---------------- kernel 2: top-2 + softmax + masks + usage + (last block) losses ----
__global__ void topk_kernel(const float* __restrict__ ew, float* __restrict__ masks,
                            float* __restrict__ tail, int M) {
    __shared__ float su[NEXP];
    __shared__ int sc;
    const int t = threadIdx.x;
    if (t < NEXP) su[t] = 0.f;
    if (t == 0)   sc = 0;
    __syncthreads();
    const int tok = blockIdx.x * blockDim.x + t;
    if (tok < M) {
        float v[NEXP];
        float4 a = *(const float4*)(ew + (size_t)tok * NEXP);
        float4 b = *(const float4*)(ew + (size_t)tok * NEXP + 4);
        v[0]=a.x; v[1]=a.y; v[2]=a.z; v[3]=a.w; v[4]=b.x; v[5]=b.y; v[6]=b.z; v[7]=b.w;
        int i1 = 0; float m1 = v[0];
#pragma unroll
        for (int e = 1; e < NEXP; ++e) if (v[e] > m1) { m1 = v[e]; i1 = e; }
        int i2 = -1; float m2 = -3.402823466e38f;
#pragma unroll
        for (int e = 0; e < NEXP; ++e) if (e != i1 && v[e] > m2) { m2 = v[e]; i2 = e; }
        float ex = expf(m2 - m1);
        float p1 = 1.f / (1.f + ex), p2 = ex / (1.f + ex);
        float o[NEXP];
#pragma unroll
        for (int e = 0; e < NEXP; ++e) o[e] = (e == i1) ? p1 : ((e == i2) ? p2 : 0.f);
        *(float4*)(masks + (size_t)tok * NEXP)     = make_float4(o[0], o[1], o[2], o[3]);
        *(float4*)(masks + (size_t)tok * NEXP + 4) = make_float4(o[4], o[5], o[6], o[7]);
        atomicAdd(&su[i1], p1);
        atomicAdd(&su[i2], p2);
        atomicAdd(&sc, (p1 > 0.f) + (p2 > 0.f));
    }
    __syncthreads();
    if (t < NEXP) atomicAdd(&g_usage[t], su[t]);
    if (t == 0)   atomicAdd(&g_count, sc);
    __threadfence();
    __syncthreads();
    if (t == 0 && atomicAdd(&g_done, 1) == (int)gridDim.x - 1) {
        __threadfence();
        float u[NEXP], s = 0.f;
#pragma unroll
        for (int e = 0; e < NEXP; ++e) { u[e] = g_usage[e]; s += u[e]; }
        float lb = 0.f;
#pragma unroll
        for (int e = 0; e < NEXP; ++e) {
            float un = u[e] / s;
            tail[1 + e] = un;
            float d = un - 0.125f;
            lb += d * d;
        }
        lb *= (1.f / 8.f);
        float sp = ((float)g_count / (float)M) * 0.5f;
        tail[0] = lb + 0.1f * sp;
    }
}

// ---------------- launch ----------------
extern "C" void kernel_launch(void* const* d_in, const int* in_sizes, int n_in,
                              void* d_out, int out_size) {
    const float* x  = (const float*)d_in[0];
    const float* w1 = (const float*)d_in[1];
    const float* b1 = (const float*)d_in[2];
    const float* w2 = (const float*)d_in[3];
    const float* b2 = (const float*)d_in[4];

    float* out   = (float*)d_out;
    const int M  = in_sizes[0] / HDIM;            // 16384
    float* ew    = out;
    float* masks = out + (size_t)M * NEXP;
    float* tail  = out + (size_t)2 * M * NEXP;

    cudaFuncSetAttribute(gemm_kernel, cudaFuncAttributeMaxDynamicSharedMemorySize, SMEM_DYN);

    pre_kernel<<<2048 + (M * NEXP + 255) / 256, 256>>>(w1, ew, b2);
    gemm_kernel<<<dim3(NDIM / BN, M / BM), 256, SMEM_DYN>>>(x, b1, w2, ew);
    topk_kernel<<<(M + 255) / 256, 256>>>(ew, masks, tail, M);
}